// round 16
// baseline (speedup 1.0000x reference)
#include <cuda_runtime.h>
#include <cuda_fp16.h>
#include <cstdint>
#include <cstdio>

#define Bb   2
#define Ss   2048
#define Dd   2048
#define Hh   32
#define HDd  64
#define MBb  16
#define Nsteps 128
#define EPSf 1e-5f

typedef unsigned long long ull;

// ---------------- scratch (static device arrays; no allocation) ----------------
__device__ float  g_q[Bb*Ss*Dd];      // fp32 rope'd q (output-add path)
__device__ float  g_y[Bb*Ss*Dd];
__device__ float  g_lr[Bb*Hh*Ss];     // h-major
__device__ __half g_xh[Bb*Ss*Dd];     // fp16 activations (x, then postln output)
__device__ __half g_wh[4*Dd*Dd];      // fp16 weights Wq|Wk|Wv|Wo
__device__ __half g_qh[Bb*Ss*Dd];     // fp16 rope'd q
__device__ __half g_kh[Bb*Ss*Dd];     // fp16 rope'd k
__device__ __half g_vh[Bb*Ss*Dd];     // fp16 rope'd v
__device__ float2 g_rope[Ss*32];

// ---------------- PTX helpers ----------------
__device__ __forceinline__ uint32_t smem_u32(const void* p){
    uint32_t a;
    asm("{ .reg .u64 t; cvta.to.shared.u64 t, %1; cvt.u32.u64 %0, t; }" : "=r"(a) : "l"(p));
    return a;
}
__device__ __forceinline__ void cpasync16(uint32_t s, const void* g){
    asm volatile("cp.async.cg.shared.global [%0], [%1], 16;" :: "r"(s), "l"(g) : "memory");
}
#define CP_COMMIT() asm volatile("cp.async.commit_group;" ::: "memory")
#define CP_WAIT(n)  asm volatile("cp.async.wait_group %0;" :: "n"(n) : "memory")

__device__ __forceinline__ void ldsm4(uint32_t* r, uint32_t a){
    asm volatile("ldmatrix.sync.aligned.m8n8.x4.shared.b16 {%0,%1,%2,%3}, [%4];"
        : "=r"(r[0]), "=r"(r[1]), "=r"(r[2]), "=r"(r[3]) : "r"(a));
}
__device__ __forceinline__ void ldsm2(uint32_t* r, uint32_t a){
    asm volatile("ldmatrix.sync.aligned.m8n8.x2.shared.b16 {%0,%1}, [%2];"
        : "=r"(r[0]), "=r"(r[1]) : "r"(a));
}
__device__ __forceinline__ void ldsm2t(uint32_t* r, uint32_t a){
    asm volatile("ldmatrix.sync.aligned.m8n8.x2.trans.shared.b16 {%0,%1}, [%2];"
        : "=r"(r[0]), "=r"(r[1]) : "r"(a));
}
__device__ __forceinline__ void mma16816(float* d, const uint32_t* a, const uint32_t* b){
    asm volatile("mma.sync.aligned.m16n8k16.row.col.f32.f16.f16.f32 "
        "{%0,%1,%2,%3}, {%4,%5,%6,%7}, {%8,%9}, {%0,%1,%2,%3};"
        : "+f"(d[0]), "+f"(d[1]), "+f"(d[2]), "+f"(d[3])
        : "r"(a[0]), "r"(a[1]), "r"(a[2]), "r"(a[3]), "r"(b[0]), "r"(b[1]));
}
__device__ __forceinline__ ull pk2(float lo, float hi){
    ull r; asm("mov.b64 %0, {%1, %2};" : "=l"(r) : "f"(lo), "f"(hi)); return r;
}
__device__ __forceinline__ ull ffma2(ull a, ull b, ull c){
    ull d; asm("fma.rn.f32x2 %0, %1, %2, %3;" : "=l"(d) : "l"(a), "l"(b), "l"(c)); return d;
}
__device__ __forceinline__ void up2(ull v, float& lo, float& hi){
    asm("mov.b64 {%0, %1}, %2;" : "=f"(lo), "=f"(hi) : "l"(v));
}
__device__ __forceinline__ ull dup2(float x){ return pk2(x, x); }

// ---------------- fp32 -> fp16 (activations) ----------------
__global__ __launch_bounds__(256)
void half_kernel(const float* __restrict__ src, __half* __restrict__ hi, int n4)
{
    int i = blockIdx.x * blockDim.x + threadIdx.x;
    if (i >= n4) return;
    float4 v = reinterpret_cast<const float4*>(src)[i];
    __half2* hp = reinterpret_cast<__half2*>(hi + (size_t)i*4);
    hp[0] = __halves2half2(__float2half_rn(v.x), __float2half_rn(v.y));
    hp[1] = __halves2half2(__float2half_rn(v.z), __float2half_rn(v.w));
}

// ---------------- fp32 -> fp16 for the 4 weight matrices, one launch ----------------
__global__ __launch_bounds__(256)
void halfw_kernel(const float* __restrict__ W0s, const float* __restrict__ W1s,
                  const float* __restrict__ W2s, const float* __restrict__ W3s,
                  __half* __restrict__ dst, int n4)
{
    int i = blockIdx.x * blockDim.x + threadIdx.x;
    if (i >= n4) return;
    int z = blockIdx.z;
    const float* src = (z == 0) ? W0s : (z == 1) ? W1s : (z == 2) ? W2s : W3s;
    float4 v = reinterpret_cast<const float4*>(src)[i];
    __half2* hp = reinterpret_cast<__half2*>(dst + (size_t)z*Dd*Dd + (size_t)i*4);
    hp[0] = __halves2half2(__float2half_rn(v.x), __float2half_rn(v.y));
    hp[1] = __halves2half2(__float2half_rn(v.z), __float2half_rn(v.w));
}

// ---------------- RoPE cos/sin table ----------------
__global__ __launch_bounds__(256)
void ropetab_kernel(const float* __restrict__ pf)
{
    int i = blockIdx.x * 256 + threadIdx.x;
    float f = pf[i], s, c;
    sincosf(f, &s, &c);
    g_rope[i] = make_float2(c, s);
}

// ---------------- HMMA fp16 NT GEMM: 256x128 CTA tile ----------------
#define BMt 256
#define BNt 128
#define BKt 32
#define RSB 80
#define ATILE_B (256*RSB)
#define BTILE_B (128*RSB)
#define STAGE_B (ATILE_B + BTILE_B)
#define GSMEM  (3*STAGE_B)

template<bool ROPE>
__global__ __launch_bounds__(256, 1)
void gemm_fp16(const __half* __restrict__ Ah, const __half* __restrict__ Bh,
               float* __restrict__ C,
               __half* __restrict__ Hq, __half* __restrict__ Hk, __half* __restrict__ Hv)
{
    extern __shared__ char sm[];
    const uint32_t sb0 = smem_u32(sm);
    const int tid = threadIdx.x, lane = tid & 31, wid = tid >> 5;
    const int wm = wid & 3, wn = wid >> 2;
    const int z = blockIdx.z;
    const __half* bhp = Bh + (size_t)z * Dd * Dd;
    __half* Hp = (z == 0) ? Hq : (z == 1) ? Hk : Hv;
    const int bm = blockIdx.y * BMt, bn = blockIdx.x * BNt;

    const int lr = tid >> 1;
    const int lc = (tid & 1) * 2;

    auto load_stage = [&](int s, int kt){
        const uint32_t st = sb0 + s * STAGE_B;
        const int kel = kt * BKt + lc * 8;
        #pragma unroll
        for (int p = 0; p < 2; p++){
            const int r = lr + p * 128;
            const __half* gh = Ah + (size_t)(bm + r) * Dd + kel;
            const uint32_t sa = st + r * RSB + lc * 16;
            cpasync16(sa, gh);  cpasync16(sa + 16, gh + 8);
        }
        {
            const __half* gh = bhp + (size_t)(bn + lr) * Dd + kel;
            const uint32_t sa = st + ATILE_B + lr * RSB + lc * 16;
            cpasync16(sa, gh);  cpasync16(sa + 16, gh + 8);
        }
    };

    float acc[4][8][4];
    #pragma unroll
    for (int i = 0; i < 4; i++)
        #pragma unroll
        for (int j = 0; j < 8; j++)
            #pragma unroll
            for (int u = 0; u < 4; u++) acc[i][j][u] = 0.f;

    const int arow_l = (lane & 15);
    const int acol   = (lane >> 4) * 16;
    const int brow_l = (lane & 7) + ((lane & 16) >> 1);
    const int bcol   = ((lane >> 3) & 1) * 16;

    auto compute_stage = [&](int s){
        const uint32_t st = sb0 + s * STAGE_B;
        #pragma unroll
        for (int ks = 0; ks < 2; ks++){
            const int kb = ks * 32;
            uint32_t ah[4][4], bh4[4][4];
            #pragma unroll
            for (int mt = 0; mt < 4; mt++){
                const uint32_t ra = st + (wm*64 + mt*16 + arow_l) * RSB + kb + acol;
                ldsm4(ah[mt], ra);
            }
            #pragma unroll
            for (int nb = 0; nb < 4; nb++){
                const uint32_t rb = st + ATILE_B + (wn*64 + nb*16 + brow_l) * RSB + kb + bcol;
                ldsm4(bh4[nb], rb);
            }
            #pragma unroll
            for (int mt = 0; mt < 4; mt++){
                #pragma unroll
                for (int nt = 0; nt < 8; nt++){
                    const int nb = nt >> 1, pr = (nt & 1) * 2;
                    uint32_t bfh[2] = { bh4[nb][pr], bh4[nb][pr+1] };
                    mma16816(acc[mt][nt], ah[mt], bfh);
                }
            }
        }
    };

    const int niter = Dd / BKt;
    load_stage(0, 0); CP_COMMIT();
    load_stage(1, 1); CP_COMMIT();
    for (int kt = 0; kt < niter; kt++){
        CP_WAIT(1);
        __syncthreads();
        if (kt + 2 < niter){ load_stage((kt + 2) % 3, kt + 2); CP_COMMIT(); }
        else               { CP_COMMIT(); }
        compute_stage(kt % 3);
    }

    #pragma unroll
    for (int mt = 0; mt < 4; mt++){
        const int m = bm + wm*64 + mt*16 + (lane >> 2);
        const int s0 = m & (Ss - 1), s1 = (m + 8) & (Ss - 1);
        #pragma unroll
        for (int nt = 0; nt < 8; nt++){
            const int n = bn + wn*64 + nt*8 + 2*(lane & 3);
            if (ROPE){
                const int p = (n >> 1) & 31;
                float2 cs0 = g_rope[s0*32 + p];
                float2 cs1 = g_rope[s1*32 + p];
                float a0 = acc[mt][nt][0], a1 = acc[mt][nt][1];
                float2 w0 = make_float2(a0*cs0.x - a1*cs0.y, a0*cs0.y + a1*cs0.x);
                a0 = acc[mt][nt][2]; a1 = acc[mt][nt][3];
                float2 w1 = make_float2(a0*cs1.x - a1*cs1.y, a0*cs1.y + a1*cs1.x);
                if (z == 0){
                    *reinterpret_cast<float2*>(C + (size_t)m * Dd + n) = w0;
                    *reinterpret_cast<float2*>(C + (size_t)(m + 8) * Dd + n) = w1;
                }
                *reinterpret_cast<__half2*>(Hp + (size_t)m * Dd + n) =
                    __halves2half2(__float2half_rn(w0.x), __float2half_rn(w0.y));
                *reinterpret_cast<__half2*>(Hp + (size_t)(m + 8) * Dd + n) =
                    __halves2half2(__float2half_rn(w1.x), __float2half_rn(w1.y));
            } else {
                *reinterpret_cast<float2*>(C + (size_t)m * Dd + n) =
                    make_float2(acc[mt][nt][0], acc[mt][nt][1]);
                *reinterpret_cast<float2*>(C + (size_t)(m + 8) * Dd + n) =
                    make_float2(acc[mt][nt][2], acc[mt][nt][3]);
            }
        }
    }
}

// ---------------- learning-rate scalars, 8 tokens/block ----------------
#define LRTOK 8
__global__ __launch_bounds__(256)
void lr_kernel(const float* __restrict__ x, const float* __restrict__ ilrW,
               const float* __restrict__ ilrb)
{
    extern __shared__ float xs[];
    const int tokb = blockIdx.x * LRTOK;
    for (int i = threadIdx.x; i < LRTOK * Dd; i += 256)
        xs[i] = x[(size_t)tokb * Dd + i];
    __syncthreads();
    const int w = threadIdx.x >> 5, lane = threadIdx.x & 31;
    for (int h = w; h < Hh; h += 8){
        const float* wr = ilrW + (size_t)h * Dd;
        float s[LRTOK];
        #pragma unroll
        for (int t = 0; t < LRTOK; t++) s[t] = 0.f;
        for (int m = lane; m < Dd; m += 32){
            float wv = wr[m];
            #pragma unroll
            for (int t = 0; t < LRTOK; t++) s[t] = fmaf(xs[t*Dd + m], wv, s[t]);
        }
        #pragma unroll
        for (int t = 0; t < LRTOK; t++){
            #pragma unroll
            for (int o = 16; o; o >>= 1) s[t] += __shfl_xor_sync(0xffffffffu, s[t], o);
        }
        if (lane < LRTOK){
            float tval = s[lane] + ilrb[h];
            int tok = tokb + lane;
            int b2 = tok >> 11, s2 = tok & (Ss - 1);
            g_lr[((size_t)b2 * Hh + h) * Ss + s2] =
                (1.0f / (1.0f + expf(-tval))) * (1.0f / (float)HDd);
        }
    }
}

// ---------------- sequential TTT scan v5 ----------------
// fp32 (floats): XQs[2*1088] Wm[4096] Grs[1056] Zs[1088] ZQs[1088]
//                bbA/bbB/gvv/bev[256] Ccs[272] lrs[32] gsv[16] = 10080 floats (40320 B)
// fp16 (byte offsets): Wh@40320 (64x144B) QH@49536 KH@54144 VH@58752 (each 2x16x144B)
#define SR2 68
#define TILEF (16*SR2)
#define GRS 66
#define SCAN_F32 10080
#define WH_OFF  (SCAN_F32*4)            // 40320
#define QH_OFF  (WH_OFF + 64*144)       // 49536
#define KH_OFF  (QH_OFF + 2*16*144)     // 54144
#define VH_OFF  (KH_OFF + 2*16*144)     // 58752
#define SCAN_SMEM_BYTES (VH_OFF + 2*16*144)   // 63360

__global__ __launch_bounds__(512, 1)
void scan_kernel(const float* __restrict__ lgs, const float* __restrict__ tg,
                 const float* __restrict__ tb,  const float* __restrict__ W0,
                 const float* __restrict__ b0)
{
    extern __shared__ float sms[];
    float* XQs = sms;                  // 2*1088
    float* Wm  = XQs + 2*TILEF;        // 4096
    float* Grs = Wm + 4096;            // 1056
    float* Zs  = Grs + 16*GRS;         // 1088
    float* ZQs = Zs + 16*SR2;          // 1088
    float* bbA = ZQs + 16*SR2;
    float* bbB = bbA + 64;
    float* gvv = bbB + 64;
    float* bev = gvv + 64;
    float* Ccs = bev + 64;             // 272
    float* lrs = Ccs + 16*17;          // 32
    float* gsv = lrs + 32;             // 16

    const uint32_t sbase = smem_u32(sms);
    __half* WhP = (__half*)((char*)sms + WH_OFF);

    const int bh = blockIdx.x;
    const int b = bh >> 5, h = bh & 31;
    const int tid = threadIdx.x, w = tid >> 5, lane = tid & 31;

    for (int i = tid; i < 4096; i += 512){
        float wv = W0[h*4096 + i];
        Wm[i] = wv;
        int k = i >> 6, c = i & 63;
        WhP[k*72 + c] = __float2half_rn(wv);
    }
    if (tid < 64){ bbA[tid] = b0[h*64 + tid]; gvv[tid] = tg[h*64 + tid]; bev[tid] = tb[h*64 + tid]; }
    if (tid < 16) gsv[tid] = fmaxf(1.0f / (float)(tid + 1) + lgs[tid], 0.0f);
    if (tid < 256){                   // zero upper triangle of Cc once
        int i = tid >> 4, j = tid & 15;
        if (j > i) Ccs[i*17 + j] = 0.f;
    }

    const size_t base = (size_t)b * Ss * Dd + h * HDd;
    const float* lrg = g_lr + ((size_t)b * Hh + h) * Ss;

    const uint32_t sXQ = sbase;
    const uint32_t sLR = smem_u32(lrs);
    const uint32_t sWh = sbase + WH_OFF;
    const uint32_t sQH = sbase + QH_OFF;
    const uint32_t sKH = sbase + KH_OFF;
    const uint32_t sVH = sbase + VH_OFF;

    auto prefetch = [&](int n){
        const int bs = n & 1;
        #pragma unroll
        for (int pass = 0; pass < 2; pass++){
            int idx = tid + pass * 512;
            if (idx < 256){
                int r = (idx >> 4) & 15;
                int c = idx & 15;
                const float* gp = g_q + base + (size_t)(n*MBb + r) * Dd + c*4;
                uint32_t sa = sXQ + (bs*TILEF + r*SR2 + c*4) * 4;
                cpasync16(sa, gp);
            } else if (idx < 640){
                int e = idx - 256;           // 0..383
                int t2 = e >> 7;             // 0=qh, 1=kh, 2=vh
                int r = (e >> 3) & 15;
                int c = e & 7;
                const __half* gp = (t2 == 0 ? g_qh : t2 == 1 ? g_kh : g_vh)
                                   + base + (size_t)(n*MBb + r) * Dd + c*8;
                uint32_t sa = (t2 == 0 ? sQH : t2 == 1 ? sKH : sVH) + bs*2304 + r*144 + c*16;
                cpasync16(sa, gp);
            }
        }
        if (tid < 4) cpasync16(sLR + (bs*16 + tid*4)*4, lrg + n*MBb + tid*4);
    };

    prefetch(0); CP_COMMIT();
    __syncthreads();

    float2 gv2 = *reinterpret_cast<const float2*>(gvv + 2*lane);
    float2 be2 = *reinterpret_cast<const float2*>(bev + 2*lane);
    float2 bb2 = make_float2(0.f, 0.f);

    for (int n = 0; n < Nsteps; n++){
        CP_WAIT(0);
        __syncthreads();
        const int bs = n & 1;
        if (n + 1 < Nsteps) prefetch(n + 1);
        CP_COMMIT();

        const float* XQb = XQs + bs*TILEF;
        const float* lrb = lrs + bs*16;
        float* bbr = (n & 1) ? bbB : bbA;
        float* bbw = (n & 1) ? bbA : bbB;
        const uint32_t qh = sQH + bs*2304;
        const uint32_t kh = sKH + bs*2304;
        const __half* KHp = (const __half*)((char*)sms + KH_OFF + bs*2304);
        const __half* VHp = (const __half*)((char*)sms + VH_OFF + bs*2304);

        // ============ phase A: tensor-core matmuls ============
        {
            const bool isZ = (w < 8);
            const int n0 = 8 * (isZ ? w : (w - 8));
            const uint32_t aaddr = (isZ ? kh : qh) + (lane & 15)*144 + (lane >> 4)*16;
            const uint32_t baddr = sWh + ((lane & 7) + ((lane >> 3) & 1)*8)*144 + n0*2;
            float acc[4] = {0.f, 0.f, 0.f, 0.f};
            #pragma unroll
            for (int ks = 0; ks < 4; ks++){
                uint32_t a4[4]; ldsm4(a4, aaddr + ks*32);
                uint32_t b2[2]; ldsm2t(b2, baddr + ks*16*144);
                mma16816(acc, a4, b2);
            }
            float* dst = isZ ? Zs : ZQs;
            const int row = lane >> 2, col = n0 + 2*(lane & 3);
            *reinterpret_cast<float2*>(dst + row*SR2 + col)     = make_float2(acc[0], acc[1]);
            *reinterpret_cast<float2*>(dst + (row+8)*SR2 + col) = make_float2(acc[2], acc[3]);

            if (w == 8 || w == 9){
                const int n0a = 8 * (w - 8);
                const uint32_t aq = qh + (lane & 15)*144 + (lane >> 4)*16;
                const uint32_t bk = kh + (n0a + (lane & 7))*144 + ((lane >> 3) & 1)*16;
                float at[4] = {0.f, 0.f, 0.f, 0.f};
                #pragma unroll
                for (int ks = 0; ks < 4; ks++){
                    uint32_t a4[4]; ldsm4(a4, aq + ks*32);
                    uint32_t b2[2]; ldsm2(b2, bk + ks*32);
                    mma16816(at, a4, b2);
                }
                const int i0 = lane >> 2, j0 = n0a + 2*(lane & 3);
                #pragma unroll
                for (int u = 0; u < 4; u++){
                    const int i = i0 + (u >> 1)*8, j = j0 + (u & 1);
                    if (j <= i) Ccs[i*17 + j] = gsv[i] * lrb[j] * (at[u] + 1.f);
                }
            }
        }
        __syncthreads();

        // ============ phase B: grad, one row per warp ============
        {
            const int r = w;
            bb2 = *reinterpret_cast<const float2*>(bbr + 2*lane);
            float2 zf = *reinterpret_cast<const float2*>(Zs + r*SR2 + 2*lane);
            float zx = zf.x + bb2.x, zy = zf.y + bb2.y;
            float s1r = zx + zy, s2r = zx*zx + zy*zy;
            #pragma unroll
            for (int o = 16; o; o >>= 1){
                s1r += __shfl_xor_sync(0xffffffffu, s1r, o);
                s2r += __shfl_xor_sync(0xffffffffu, s2r, o);
            }
            float mu = s1r * (1.0f/64.0f);
            float var = s2r * (1.0f/64.0f) - mu*mu;
            float rstd = rsqrtf(var + EPSf);
            float zhx = (zx - mu) * rstd, zhy = (zy - mu) * rstd;
            float2 xv = __half22float2(*reinterpret_cast<const __half2*>(
                        (const char*)VHp + r*144 + 4*lane));
            float2 xk = __half22float2(*reinterpret_cast<const __half2*>(
                        (const char*)KHp + r*144 + 4*lane));
            float dyx = fmaf(gv2.x, zhx, be2.x) - (xv.x - xk.x);
            float dyy = fmaf(gv2.y, zhy, be2.y) - (xv.y - xk.y);
            float dzx = dyx * gv2.x, dzy = dyy * gv2.y;
            float m1 = dzx + dzy, m2 = fmaf(dzx, zhx, dzy*zhy);
            #pragma unroll
            for (int o = 16; o; o >>= 1){
                m1 += __shfl_xor_sync(0xffffffffu, m1, o);
                m2 += __shfl_xor_sync(0xffffffffu, m2, o);
            }
            m1 *= (1.0f/64.0f); m2 *= (1.0f/64.0f);
            float grx = (dzx - m1 - zhx*m2) * rstd;
            float gry = (dzy - m1 - zhy*m2) * rstd;
            *reinterpret_cast<float2*>(Grs + r*GRS + 2*lane) = make_float2(grx, gry);
        }
        __syncthreads();

        // ============ phase C ============
        if (w < 8){
            const int rA = w, rB = 15 - w;
            float2 pqA = *reinterpret_cast<const float2*>(ZQs + rA*SR2 + 2*lane);
            float2 pqB = *reinterpret_cast<const float2*>(ZQs + rB*SR2 + 2*lane);
            float axA = pqA.x + bb2.x, ayA = pqA.y + bb2.y;
            float axB = pqB.x + bb2.x, ayB = pqB.y + bb2.y;
            #pragma unroll
            for (int j = 0; j < 16; j++){                 // zero-padded Cc kills j>r terms
                float cA = Ccs[rA*17 + j];
                float cB = Ccs[rB*17 + j];
                float2 gr = *reinterpret_cast<const float2*>(Grs + j*GRS + 2*lane);
                axA = fmaf(-cA, gr.x, axA);  ayA = fmaf(-cA, gr.y, ayA);
                axB = fmaf(-cB, gr.x, axB);  ayB = fmaf(-cB, gr.y, ayB);
            }
            #pragma unroll
            for (int rr = 0; rr < 2; rr++){
                const int r = rr ? rB : rA;
                float ax = rr ? axB : axA, ay = rr ? ayB : ayA;
                float s1r = ax + ay, s2r = ax*ax + ay*ay;
                #pragma unroll
                for (int o = 16; o; o >>= 1){
                    s1r += __shfl_xor_sync(0xffffffffu, s1r, o);
                    s2r += __shfl_xor_sync(0xffffffffu, s2r, o);
                }
                float mu = s1r * (1.0f/64.0f);
                float var = s2r * (1.0f/64.0f) - mu*mu;
                float rstd = rsqrtf(var + EPSf);
                float2 xq = *reinterpret_cast<const float2*>(XQb + r*SR2 + 2*lane);
                float ox = xq.x + fmaf(gv2.x * (ax - mu), rstd, be2.x);
                float oy = xq.y + fmaf(gv2.y * (ay - mu), rstd, be2.y);
                size_t go = base + (size_t)(n*MBb + r) * Dd;
                *reinterpret_cast<float2*>(g_y + go + 2*lane) = make_float2(ox, oy);
            }
        } else {
            const int u = w - 8;
            const int kr0 = u * 8;
            const float le = gsv[15];
            ull wacc[8];
            #pragma unroll
            for (int q = 0; q < 8; q++) wacc[q] = 0;
            float bx = 0.f, by = 0.f;
            if (u == 0){
                float2 bbc = *reinterpret_cast<const float2*>(bbr + 2*lane);
                bx = bbc.x; by = bbc.y;
            }
            #pragma unroll
            for (int j = 0; j < 16; j++){
                float2 gr = *reinterpret_cast<const float2*>(Grs + j*GRS + 2*lane);
                ull gru = pk2(gr.x, gr.y);
                float cj = le * lrb[j];
                #pragma unroll
                for (int q = 0; q < 8; q++){
                    float t = cj * __half2float(KHp[j*72 + kr0 + q]);
                    wacc[q] = ffma2(dup2(t), gru, wacc[q]);
                }
                if (u == 0){
                    bx = fmaf(-cj, gr.x, bx);
                    by = fmaf(-cj, gr.y, by);
                }
            }
            #pragma unroll
            for (int q = 0; q < 8; q++){
                float wx, wy; up2(wacc[q], wx, wy);
                float2* wp = reinterpret_cast<float2*>(Wm + (kr0+q)*64 + 2*lane);
                float2 wv = *wp;
                wv.x -= wx; wv.y -= wy;
                *wp = wv;
                *reinterpret_cast<__half2*>((char*)sms + WH_OFF + (kr0+q)*144 + 4*lane) =
                    __halves2half2(__float2half_rn(wv.x), __float2half_rn(wv.y));
            }
            if (u == 0) *reinterpret_cast<float2*>(bbw + 2*lane) = make_float2(bx, by);
        }
        // next-iteration top __syncthreads covers all phase-C writes
    }
}

// ---------------- final layernorm over D, writes fp16 ----------------
__global__ __launch_bounds__(256)
void postln_half_kernel(const float* __restrict__ yin, const float* __restrict__ gmm,
                        const float* __restrict__ bta)
{
    __shared__ float red[8];
    int row = blockIdx.x, tid = threadIdx.x;
    const float* r = yin + (size_t)row * Dd;
    float vals[8];
    float s = 0.f;
    #pragma unroll
    for (int i = 0; i < 8; i++){ vals[i] = r[tid + 256*i]; s += vals[i]; }
    #pragma unroll
    for (int o = 16; o; o >>= 1) s += __shfl_xor_sync(0xffffffffu, s, o);
    if ((tid & 31) == 0) red[tid >> 5] = s;
    __syncthreads();
    float tot = 0.f;
    #pragma unroll
    for (int i = 0; i < 8; i++) tot += red[i];
    float mu = tot * (1.0f / (float)Dd);
    __syncthreads();
    float vs = 0.f;
    #pragma unroll
    for (int i = 0; i < 8; i++){ float d = vals[i] - mu; vs = fmaf(d, d, vs); }
    #pragma unroll
    for (int o = 16; o; o >>= 1) vs += __shfl_xor_sync(0xffffffffu, vs, o);
    if ((tid & 31) == 0) red[tid >> 5] = vs;
    __syncthreads();
    float vtot = 0.f;
    #pragma unroll
    for (int i = 0; i < 8; i++) vtot += red[i];
    float rstd = rsqrtf(vtot * (1.0f / (float)Dd) + EPSf);
    #pragma unroll
    for (int i = 0; i < 8; i++){
        int c = tid + 256*i;
        float val = fmaf(gmm[c] * (vals[i] - mu), rstd, bta[c]);
        g_xh[(size_t)row * Dd + c] = __float2half_rn(val);
    }
}

// ---------------- launch ----------------
extern "C" void kernel_launch(void* const* d_in, const int* in_sizes, int n_in,
                              void* d_out, int out_size)
{
    const float* x    = (const float*)d_in[0];
    const float* pf   = (const float*)d_in[1];
    const float* Wq   = (const float*)d_in[2];
    const float* Wk   = (const float*)d_in[3];
    const float* Wv   = (const float*)d_in[4];
    const float* Wo   = (const float*)d_in[5];
    const float* pg   = (const float*)d_in[6];
    const float* pb   = (const float*)d_in[7];
    const float* ilrW = (const float*)d_in[8];
    const float* ilrb = (const float*)d_in[9];
    const float* lgs  = (const float*)d_in[10];
    const float* tg   = (const float*)d_in[11];
    const float* tb   = (const float*)d_in[12];
    const float* W0   = (const float*)d_in[13];
    const float* b0   = (const float*)d_in[14];
    float* outp = (float*)d_out;

    float *qp, *yp;
    __half *xh, *wh, *qhp, *khp, *vhp;
    cudaGetSymbolAddress((void**)&qp, g_q);
    cudaGetSymbolAddress((void**)&yp, g_y);
    cudaGetSymbolAddress((void**)&xh, g_xh);
    cudaGetSymbolAddress((void**)&wh, g_wh);
    cudaGetSymbolAddress((void**)&qhp, g_qh);
    cudaGetSymbolAddress((void**)&khp, g_kh);
    cudaGetSymbolAddress((void**)&vhp, g_vh);

    cudaFuncSetAttribute(gemm_fp16<true>,  cudaFuncAttributeMaxDynamicSharedMemorySize, GSMEM);
    cudaFuncSetAttribute(gemm_fp16<false>, cudaFuncAttributeMaxDynamicSharedMemorySize, GSMEM);
    cudaFuncSetAttribute(scan_kernel, cudaFuncAttributeMaxDynamicSharedMemorySize, SCAN_SMEM_BYTES);
    cudaFuncSetAttribute(lr_kernel,   cudaFuncAttributeMaxDynamicSharedMemorySize, LRTOK*Dd*4);

    const int M = Bb * Ss;
    const int nw4 = (Dd * Dd) / 4;
    const int nx4 = (M * Dd) / 4;

    half_kernel<<<(nx4 + 255)/256, 256>>>(x, xh, nx4);
    dim3 wgrid((nw4 + 255)/256, 1, 4);
    halfw_kernel<<<wgrid, 256>>>(Wq, Wk, Wv, Wo, wh, nw4);
    ropetab_kernel<<<(Ss*32)/256, 256>>>(pf);

    dim3 ggrid(Dd / BNt, M / BMt, 3);
    gemm_fp16<true><<<ggrid, 256, GSMEM>>>(xh, wh, qp, qhp, khp, vhp);

    lr_kernel<<<M / LRTOK, 256, LRTOK*Dd*4>>>(x, ilrW, ilrb);

    scan_kernel<<<Bb * Hh, 512, SCAN_SMEM_BYTES>>>(lgs, tg, tb, W0, b0);

    postln_half_kernel<<<M, 256>>>(yp, pg, pb);

    dim3 ogrid(Dd / BNt, M / BMt, 1);
    gemm_fp16<false><<<ogrid, 256, GSMEM>>>(xh, wh + 3*(size_t)Dd*Dd, outp,
                                            nullptr, nullptr, nullptr);
}

// round 17
// speedup vs baseline: 1.0920x; 1.0920x over previous
#include <cuda_runtime.h>
#include <cuda_fp16.h>
#include <cstdint>
#include <cstdio>

#define Bb   2
#define Ss   2048
#define Dd   2048
#define Hh   32
#define HDd  64
#define MBb  16
#define Nsteps 128
#define EPSf 1e-5f

typedef unsigned long long ull;

// ---------------- scratch (static device arrays; no allocation) ----------------
__device__ float  g_q[Bb*Ss*Dd];      // fp32 rope'd q (output-add path)
__device__ float  g_y[Bb*Ss*Dd];
__device__ float  g_lr[Bb*Hh*Ss];     // h-major
__device__ __half g_xh[Bb*Ss*Dd];     // fp16 activations (x, then postln output)
__device__ __half g_wh[4*Dd*Dd];      // fp16 weights Wq|Wk|Wv|Wo
__device__ __half g_qh[Bb*Ss*Dd];     // fp16 rope'd q
__device__ __half g_kh[Bb*Ss*Dd];     // fp16 rope'd k
__device__ __half g_vh[Bb*Ss*Dd];     // fp16 rope'd v
__device__ float2 g_rope[Ss*32];

// ---------------- PTX helpers ----------------
__device__ __forceinline__ uint32_t smem_u32(const void* p){
    uint32_t a;
    asm("{ .reg .u64 t; cvta.to.shared.u64 t, %1; cvt.u32.u64 %0, t; }" : "=r"(a) : "l"(p));
    return a;
}
__device__ __forceinline__ void cpasync16(uint32_t s, const void* g){
    asm volatile("cp.async.cg.shared.global [%0], [%1], 16;" :: "r"(s), "l"(g) : "memory");
}
#define CP_COMMIT() asm volatile("cp.async.commit_group;" ::: "memory")
#define CP_WAIT(n)  asm volatile("cp.async.wait_group %0;" :: "n"(n) : "memory")

__device__ __forceinline__ void ldsm4(uint32_t* r, uint32_t a){
    asm volatile("ldmatrix.sync.aligned.m8n8.x4.shared.b16 {%0,%1,%2,%3}, [%4];"
        : "=r"(r[0]), "=r"(r[1]), "=r"(r[2]), "=r"(r[3]) : "r"(a));
}
__device__ __forceinline__ void ldsm2(uint32_t* r, uint32_t a){
    asm volatile("ldmatrix.sync.aligned.m8n8.x2.shared.b16 {%0,%1}, [%2];"
        : "=r"(r[0]), "=r"(r[1]) : "r"(a));
}
__device__ __forceinline__ void ldsm2t(uint32_t* r, uint32_t a){
    asm volatile("ldmatrix.sync.aligned.m8n8.x2.trans.shared.b16 {%0,%1}, [%2];"
        : "=r"(r[0]), "=r"(r[1]) : "r"(a));
}
__device__ __forceinline__ void mma16816(float* d, const uint32_t* a, const uint32_t* b){
    asm volatile("mma.sync.aligned.m16n8k16.row.col.f32.f16.f16.f32 "
        "{%0,%1,%2,%3}, {%4,%5,%6,%7}, {%8,%9}, {%0,%1,%2,%3};"
        : "+f"(d[0]), "+f"(d[1]), "+f"(d[2]), "+f"(d[3])
        : "r"(a[0]), "r"(a[1]), "r"(a[2]), "r"(a[3]), "r"(b[0]), "r"(b[1]));
}
__device__ __forceinline__ ull pk2(float lo, float hi){
    ull r; asm("mov.b64 %0, {%1, %2};" : "=l"(r) : "f"(lo), "f"(hi)); return r;
}
__device__ __forceinline__ ull ffma2(ull a, ull b, ull c){
    ull d; asm("fma.rn.f32x2 %0, %1, %2, %3;" : "=l"(d) : "l"(a), "l"(b), "l"(c)); return d;
}
__device__ __forceinline__ void up2(ull v, float& lo, float& hi){
    asm("mov.b64 {%0, %1}, %2;" : "=f"(lo), "=f"(hi) : "l"(v));
}
__device__ __forceinline__ ull dup2(float x){ return pk2(x, x); }

// ---------------- fp32 -> fp16 (activations) ----------------
__global__ __launch_bounds__(256)
void half_kernel(const float* __restrict__ src, __half* __restrict__ hi, int n4)
{
    int i = blockIdx.x * blockDim.x + threadIdx.x;
    if (i >= n4) return;
    float4 v = reinterpret_cast<const float4*>(src)[i];
    __half2* hp = reinterpret_cast<__half2*>(hi + (size_t)i*4);
    hp[0] = __halves2half2(__float2half_rn(v.x), __float2half_rn(v.y));
    hp[1] = __halves2half2(__float2half_rn(v.z), __float2half_rn(v.w));
}

// ---------------- fp32 -> fp16 for the 4 weight matrices, one launch ----------------
__global__ __launch_bounds__(256)
void halfw_kernel(const float* __restrict__ W0s, const float* __restrict__ W1s,
                  const float* __restrict__ W2s, const float* __restrict__ W3s,
                  __half* __restrict__ dst, int n4)
{
    int i = blockIdx.x * blockDim.x + threadIdx.x;
    if (i >= n4) return;
    int z = blockIdx.z;
    const float* src = (z == 0) ? W0s : (z == 1) ? W1s : (z == 2) ? W2s : W3s;
    float4 v = reinterpret_cast<const float4*>(src)[i];
    __half2* hp = reinterpret_cast<__half2*>(dst + (size_t)z*Dd*Dd + (size_t)i*4);
    hp[0] = __halves2half2(__float2half_rn(v.x), __float2half_rn(v.y));
    hp[1] = __halves2half2(__float2half_rn(v.z), __float2half_rn(v.w));
}

// ---------------- RoPE cos/sin table ----------------
__global__ __launch_bounds__(256)
void ropetab_kernel(const float* __restrict__ pf)
{
    int i = blockIdx.x * 256 + threadIdx.x;
    float f = pf[i], s, c;
    sincosf(f, &s, &c);
    g_rope[i] = make_float2(c, s);
}

// ---------------- HMMA fp16 NT GEMM: 128x128 CTA tile, 4 stages, 2 CTA/SM --------
#define BMt 128
#define BNt 128
#define BKt 32
#define RSB 80
#define ATILE_B (128*RSB)       // 10240
#define BTILE_B (128*RSB)       // 10240
#define STAGE_B (ATILE_B + BTILE_B)   // 20480
#define NSTG 4
#define GSMEM  (NSTG*STAGE_B)   // 81920

template<bool ROPE>
__global__ __launch_bounds__(256, 2)
void gemm_fp16(const __half* __restrict__ Ah, const __half* __restrict__ Bh,
               float* __restrict__ C,
               __half* __restrict__ Hq, __half* __restrict__ Hk, __half* __restrict__ Hv)
{
    extern __shared__ char sm[];
    const uint32_t sb0 = smem_u32(sm);
    const int tid = threadIdx.x, lane = tid & 31, wid = tid >> 5;
    const int wm = wid & 1, wn = wid >> 1;          // 2 x 4 warp grid, 64x32 warp tile
    const int z = blockIdx.z;
    const __half* bhp = Bh + (size_t)z * Dd * Dd;
    __half* Hp = (z == 0) ? Hq : (z == 1) ? Hk : Hv;
    const int bm = blockIdx.y * BMt, bn = blockIdx.x * BNt;

    const int lr = tid >> 1;            // 0..127
    const int lc = (tid & 1) * 2;

    auto load_stage = [&](int s, int kt){
        const uint32_t st = sb0 + s * STAGE_B;
        const int kel = kt * BKt + lc * 8;
        {
            const __half* gh = Ah + (size_t)(bm + lr) * Dd + kel;
            const uint32_t sa = st + lr * RSB + lc * 16;
            cpasync16(sa, gh);  cpasync16(sa + 16, gh + 8);
        }
        {
            const __half* gh = bhp + (size_t)(bn + lr) * Dd + kel;
            const uint32_t sa = st + ATILE_B + lr * RSB + lc * 16;
            cpasync16(sa, gh);  cpasync16(sa + 16, gh + 8);
        }
    };

    float acc[4][4][4];
    #pragma unroll
    for (int i = 0; i < 4; i++)
        #pragma unroll
        for (int j = 0; j < 4; j++)
            #pragma unroll
            for (int u = 0; u < 4; u++) acc[i][j][u] = 0.f;

    const int arow_l = (lane & 15);
    const int acol   = (lane >> 4) * 16;
    const int brow_l = (lane & 7) + ((lane & 16) >> 1);
    const int bcol   = ((lane >> 3) & 1) * 16;

    auto compute_stage = [&](int s){
        const uint32_t st = sb0 + s * STAGE_B;
        #pragma unroll
        for (int ks = 0; ks < 2; ks++){
            const int kb = ks * 32;
            uint32_t ah[4][4], bh4[2][4];
            #pragma unroll
            for (int mt = 0; mt < 4; mt++){
                const uint32_t ra = st + (wm*64 + mt*16 + arow_l) * RSB + kb + acol;
                ldsm4(ah[mt], ra);
            }
            #pragma unroll
            for (int nb = 0; nb < 2; nb++){
                const uint32_t rb = st + ATILE_B + (wn*32 + nb*16 + brow_l) * RSB + kb + bcol;
                ldsm4(bh4[nb], rb);
            }
            #pragma unroll
            for (int mt = 0; mt < 4; mt++){
                #pragma unroll
                for (int nt = 0; nt < 4; nt++){
                    const int nb = nt >> 1, pr = (nt & 1) * 2;
                    uint32_t bfh[2] = { bh4[nb][pr], bh4[nb][pr+1] };
                    mma16816(acc[mt][nt], ah[mt], bfh);
                }
            }
        }
    };

    const int niter = Dd / BKt;    // 64
    load_stage(0, 0); CP_COMMIT();
    load_stage(1, 1); CP_COMMIT();
    load_stage(2, 2); CP_COMMIT();
    for (int kt = 0; kt < niter; kt++){
        CP_WAIT(2);                 // stage kt resident, 2 groups may stay in flight
        __syncthreads();
        if (kt + 3 < niter){ load_stage((kt + 3) % NSTG, kt + 3); CP_COMMIT(); }
        else               { CP_COMMIT(); }
        compute_stage(kt % NSTG);
    }

    #pragma unroll
    for (int mt = 0; mt < 4; mt++){
        const int m = bm + wm*64 + mt*16 + (lane >> 2);
        const int s0 = m & (Ss - 1), s1 = (m + 8) & (Ss - 1);
        #pragma unroll
        for (int nt = 0; nt < 4; nt++){
            const int n = bn + wn*32 + nt*8 + 2*(lane & 3);
            if (ROPE){
                const int p = (n >> 1) & 31;
                float2 cs0 = g_rope[s0*32 + p];
                float2 cs1 = g_rope[s1*32 + p];
                float a0 = acc[mt][nt][0], a1 = acc[mt][nt][1];
                float2 w0 = make_float2(a0*cs0.x - a1*cs0.y, a0*cs0.y + a1*cs0.x);
                a0 = acc[mt][nt][2]; a1 = acc[mt][nt][3];
                float2 w1 = make_float2(a0*cs1.x - a1*cs1.y, a0*cs1.y + a1*cs1.x);
                if (z == 0){
                    *reinterpret_cast<float2*>(C + (size_t)m * Dd + n) = w0;
                    *reinterpret_cast<float2*>(C + (size_t)(m + 8) * Dd + n) = w1;
                }
                *reinterpret_cast<__half2*>(Hp + (size_t)m * Dd + n) =
                    __halves2half2(__float2half_rn(w0.x), __float2half_rn(w0.y));
                *reinterpret_cast<__half2*>(Hp + (size_t)(m + 8) * Dd + n) =
                    __halves2half2(__float2half_rn(w1.x), __float2half_rn(w1.y));
            } else {
                *reinterpret_cast<float2*>(C + (size_t)m * Dd + n) =
                    make_float2(acc[mt][nt][0], acc[mt][nt][1]);
                *reinterpret_cast<float2*>(C + (size_t)(m + 8) * Dd + n) =
                    make_float2(acc[mt][nt][2], acc[mt][nt][3]);
            }
        }
    }
}

// ---------------- learning-rate scalars, 8 tokens/block ----------------
#define LRTOK 8
__global__ __launch_bounds__(256)
void lr_kernel(const float* __restrict__ x, const float* __restrict__ ilrW,
               const float* __restrict__ ilrb)
{
    extern __shared__ float xs[];
    const int tokb = blockIdx.x * LRTOK;
    for (int i = threadIdx.x; i < LRTOK * Dd; i += 256)
        xs[i] = x[(size_t)tokb * Dd + i];
    __syncthreads();
    const int w = threadIdx.x >> 5, lane = threadIdx.x & 31;
    for (int h = w; h < Hh; h += 8){
        const float* wr = ilrW + (size_t)h * Dd;
        float s[LRTOK];
        #pragma unroll
        for (int t = 0; t < LRTOK; t++) s[t] = 0.f;
        for (int m = lane; m < Dd; m += 32){
            float wv = wr[m];
            #pragma unroll
            for (int t = 0; t < LRTOK; t++) s[t] = fmaf(xs[t*Dd + m], wv, s[t]);
        }
        #pragma unroll
        for (int t = 0; t < LRTOK; t++){
            #pragma unroll
            for (int o = 16; o; o >>= 1) s[t] += __shfl_xor_sync(0xffffffffu, s[t], o);
        }
        if (lane < LRTOK){
            float tval = s[lane] + ilrb[h];
            int tok = tokb + lane;
            int b2 = tok >> 11, s2 = tok & (Ss - 1);
            g_lr[((size_t)b2 * Hh + h) * Ss + s2] =
                (1.0f / (1.0f + expf(-tval))) * (1.0f / (float)HDd);
        }
    }
}

// ---------------- sequential TTT scan v5 ----------------
#define SR2 68
#define TILEF (16*SR2)
#define GRS 66
#define SCAN_F32 10080
#define WH_OFF  (SCAN_F32*4)            // 40320
#define QH_OFF  (WH_OFF + 64*144)       // 49536
#define KH_OFF  (QH_OFF + 2*16*144)     // 54144
#define VH_OFF  (KH_OFF + 2*16*144)     // 58752
#define SCAN_SMEM_BYTES (VH_OFF + 2*16*144)   // 63360

__global__ __launch_bounds__(512, 1)
void scan_kernel(const float* __restrict__ lgs, const float* __restrict__ tg,
                 const float* __restrict__ tb,  const float* __restrict__ W0,
                 const float* __restrict__ b0)
{
    extern __shared__ float sms[];
    float* XQs = sms;                  // 2*1088
    float* Wm  = XQs + 2*TILEF;        // 4096
    float* Grs = Wm + 4096;            // 1056
    float* Zs  = Grs + 16*GRS;         // 1088
    float* ZQs = Zs + 16*SR2;          // 1088
    float* bbA = ZQs + 16*SR2;
    float* bbB = bbA + 64;
    float* gvv = bbB + 64;
    float* bev = gvv + 64;
    float* Ccs = bev + 64;             // 272
    float* lrs = Ccs + 16*17;          // 32
    float* gsv = lrs + 32;             // 16

    const uint32_t sbase = smem_u32(sms);
    __half* WhP = (__half*)((char*)sms + WH_OFF);

    const int bh = blockIdx.x;
    const int b = bh >> 5, h = bh & 31;
    const int tid = threadIdx.x, w = tid >> 5, lane = tid & 31;

    for (int i = tid; i < 4096; i += 512){
        float wv = W0[h*4096 + i];
        Wm[i] = wv;
        int k = i >> 6, c = i & 63;
        WhP[k*72 + c] = __float2half_rn(wv);
    }
    if (tid < 64){ bbA[tid] = b0[h*64 + tid]; gvv[tid] = tg[h*64 + tid]; bev[tid] = tb[h*64 + tid]; }
    if (tid < 16) gsv[tid] = fmaxf(1.0f / (float)(tid + 1) + lgs[tid], 0.0f);
    if (tid < 256){
        int i = tid >> 4, j = tid & 15;
        if (j > i) Ccs[i*17 + j] = 0.f;
    }

    const size_t base = (size_t)b * Ss * Dd + h * HDd;
    const float* lrg = g_lr + ((size_t)b * Hh + h) * Ss;

    const uint32_t sXQ = sbase;
    const uint32_t sLR = smem_u32(lrs);
    const uint32_t sWh = sbase + WH_OFF;
    const uint32_t sQH = sbase + QH_OFF;
    const uint32_t sKH = sbase + KH_OFF;
    const uint32_t sVH = sbase + VH_OFF;

    auto prefetch = [&](int n){
        const int bs = n & 1;
        #pragma unroll
        for (int pass = 0; pass < 2; pass++){
            int idx = tid + pass * 512;
            if (idx < 256){
                int r = (idx >> 4) & 15;
                int c = idx & 15;
                const float* gp = g_q + base + (size_t)(n*MBb + r) * Dd + c*4;
                uint32_t sa = sXQ + (bs*TILEF + r*SR2 + c*4) * 4;
                cpasync16(sa, gp);
            } else if (idx < 640){
                int e = idx - 256;
                int t2 = e >> 7;
                int r = (e >> 3) & 15;
                int c = e & 7;
                const __half* gp = (t2 == 0 ? g_qh : t2 == 1 ? g_kh : g_vh)
                                   + base + (size_t)(n*MBb + r) * Dd + c*8;
                uint32_t sa = (t2 == 0 ? sQH : t2 == 1 ? sKH : sVH) + bs*2304 + r*144 + c*16;
                cpasync16(sa, gp);
            }
        }
        if (tid < 4) cpasync16(sLR + (bs*16 + tid*4)*4, lrg + n*MBb + tid*4);
    };

    prefetch(0); CP_COMMIT();
    __syncthreads();

    float2 gv2 = *reinterpret_cast<const float2*>(gvv + 2*lane);
    float2 be2 = *reinterpret_cast<const float2*>(bev + 2*lane);
    float2 bb2 = make_float2(0.f, 0.f);

    for (int n = 0; n < Nsteps; n++){
        CP_WAIT(0);
        __syncthreads();
        const int bs = n & 1;
        if (n + 1 < Nsteps) prefetch(n + 1);
        CP_COMMIT();

        const float* XQb = XQs + bs*TILEF;
        const float* lrb = lrs + bs*16;
        float* bbr = (n & 1) ? bbB : bbA;
        float* bbw = (n & 1) ? bbA : bbB;
        const uint32_t qh = sQH + bs*2304;
        const uint32_t kh = sKH + bs*2304;
        const __half* KHp = (const __half*)((char*)sms + KH_OFF + bs*2304);
        const __half* VHp = (const __half*)((char*)sms + VH_OFF + bs*2304);

        // ============ phase A: tensor-core matmuls ============
        {
            const bool isZ = (w < 8);
            const int n0 = 8 * (isZ ? w : (w - 8));
            const uint32_t aaddr = (isZ ? kh : qh) + (lane & 15)*144 + (lane >> 4)*16;
            const uint32_t baddr = sWh + ((lane & 7) + ((lane >> 3) & 1)*8)*144 + n0*2;
            float acc[4] = {0.f, 0.f, 0.f, 0.f};
            #pragma unroll
            for (int ks = 0; ks < 4; ks++){
                uint32_t a4[4]; ldsm4(a4, aaddr + ks*32);
                uint32_t b2[2]; ldsm2t(b2, baddr + ks*16*144);
                mma16816(acc, a4, b2);
            }
            float* dst = isZ ? Zs : ZQs;
            const int row = lane >> 2, col = n0 + 2*(lane & 3);
            *reinterpret_cast<float2*>(dst + row*SR2 + col)     = make_float2(acc[0], acc[1]);
            *reinterpret_cast<float2*>(dst + (row+8)*SR2 + col) = make_float2(acc[2], acc[3]);

            if (w == 8 || w == 9){
                const int n0a = 8 * (w - 8);
                const uint32_t aq = qh + (lane & 15)*144 + (lane >> 4)*16;
                const uint32_t bk = kh + (n0a + (lane & 7))*144 + ((lane >> 3) & 1)*16;
                float at[4] = {0.f, 0.f, 0.f, 0.f};
                #pragma unroll
                for (int ks = 0; ks < 4; ks++){
                    uint32_t a4[4]; ldsm4(a4, aq + ks*32);
                    uint32_t b2[2]; ldsm2(b2, bk + ks*32);
                    mma16816(at, a4, b2);
                }
                const int i0 = lane >> 2, j0 = n0a + 2*(lane & 3);
                #pragma unroll
                for (int u = 0; u < 4; u++){
                    const int i = i0 + (u >> 1)*8, j = j0 + (u & 1);
                    if (j <= i) Ccs[i*17 + j] = gsv[i] * lrb[j] * (at[u] + 1.f);
                }
            }
        }
        __syncthreads();

        // ============ phase B: grad, one row per warp ============
        {
            const int r = w;
            bb2 = *reinterpret_cast<const float2*>(bbr + 2*lane);
            float2 zf = *reinterpret_cast<const float2*>(Zs + r*SR2 + 2*lane);
            float zx = zf.x + bb2.x, zy = zf.y + bb2.y;
            float s1r = zx + zy, s2r = zx*zx + zy*zy;
            #pragma unroll
            for (int o = 16; o; o >>= 1){
                s1r += __shfl_xor_sync(0xffffffffu, s1r, o);
                s2r += __shfl_xor_sync(0xffffffffu, s2r, o);
            }
            float mu = s1r * (1.0f/64.0f);
            float var = s2r * (1.0f/64.0f) - mu*mu;
            float rstd = rsqrtf(var + EPSf);
            float zhx = (zx - mu) * rstd, zhy = (zy - mu) * rstd;
            float2 xv = __half22float2(*reinterpret_cast<const __half2*>(
                        (const char*)VHp + r*144 + 4*lane));
            float2 xk = __half22float2(*reinterpret_cast<const __half2*>(
                        (const char*)KHp + r*144 + 4*lane));
            float dyx = fmaf(gv2.x, zhx, be2.x) - (xv.x - xk.x);
            float dyy = fmaf(gv2.y, zhy, be2.y) - (xv.y - xk.y);
            float dzx = dyx * gv2.x, dzy = dyy * gv2.y;
            float m1 = dzx + dzy, m2 = fmaf(dzx, zhx, dzy*zhy);
            #pragma unroll
            for (int o = 16; o; o >>= 1){
                m1 += __shfl_xor_sync(0xffffffffu, m1, o);
                m2 += __shfl_xor_sync(0xffffffffu, m2, o);
            }
            m1 *= (1.0f/64.0f); m2 *= (1.0f/64.0f);
            float grx = (dzx - m1 - zhx*m2) * rstd;
            float gry = (dzy - m1 - zhy*m2) * rstd;
            *reinterpret_cast<float2*>(Grs + r*GRS + 2*lane) = make_float2(grx, gry);
        }
        __syncthreads();

        // ============ phase C ============
        if (w < 8){
            const int rA = w, rB = 15 - w;
            float2 pqA = *reinterpret_cast<const float2*>(ZQs + rA*SR2 + 2*lane);
            float2 pqB = *reinterpret_cast<const float2*>(ZQs + rB*SR2 + 2*lane);
            float axA = pqA.x + bb2.x, ayA = pqA.y + bb2.y;
            float axB = pqB.x + bb2.x, ayB = pqB.y + bb2.y;
            #pragma unroll
            for (int j = 0; j < 16; j++){
                float cA = Ccs[rA*17 + j];
                float cB = Ccs[rB*17 + j];
                float2 gr = *reinterpret_cast<const float2*>(Grs + j*GRS + 2*lane);
                axA = fmaf(-cA, gr.x, axA);  ayA = fmaf(-cA, gr.y, ayA);
                axB = fmaf(-cB, gr.x, axB);  ayB = fmaf(-cB, gr.y, ayB);
            }
            #pragma unroll
            for (int rr = 0; rr < 2; rr++){
                const int r = rr ? rB : rA;
                float ax = rr ? axB : axA, ay = rr ? ayB : ayA;
                float s1r = ax + ay, s2r = ax*ax + ay*ay;
                #pragma unroll
                for (int o = 16; o; o >>= 1){
                    s1r += __shfl_xor_sync(0xffffffffu, s1r, o);
                    s2r += __shfl_xor_sync(0xffffffffu, s2r, o);
                }
                float mu = s1r * (1.0f/64.0f);
                float var = s2r * (1.0f/64.0f) - mu*mu;
                float rstd = rsqrtf(var + EPSf);
                float2 xq = *reinterpret_cast<const float2*>(XQb + r*SR2 + 2*lane);
                float ox = xq.x + fmaf(gv2.x * (ax - mu), rstd, be2.x);
                float oy = xq.y + fmaf(gv2.y * (ay - mu), rstd, be2.y);
                size_t go = base + (size_t)(n*MBb + r) * Dd;
                *reinterpret_cast<float2*>(g_y + go + 2*lane) = make_float2(ox, oy);
            }
        } else {
            const int u = w - 8;
            const int kr0 = u * 8;
            const float le = gsv[15];
            ull wacc[8];
            #pragma unroll
            for (int q = 0; q < 8; q++) wacc[q] = 0;
            float bx = 0.f, by = 0.f;
            if (u == 0){
                float2 bbc = *reinterpret_cast<const float2*>(bbr + 2*lane);
                bx = bbc.x; by = bbc.y;
            }
            #pragma unroll
            for (int j = 0; j < 16; j++){
                float2 gr = *reinterpret_cast<const float2*>(Grs + j*GRS + 2*lane);
                ull gru = pk2(gr.x, gr.y);
                float cj = le * lrb[j];
                #pragma unroll
                for (int q = 0; q < 8; q++){
                    float t = cj * __half2float(KHp[j*72 + kr0 + q]);
                    wacc[q] = ffma2(dup2(t), gru, wacc[q]);
                }
                if (u == 0){
                    bx = fmaf(-cj, gr.x, bx);
                    by = fmaf(-cj, gr.y, by);
                }
            }
            #pragma unroll
            for (int q = 0; q < 8; q++){
                float wx, wy; up2(wacc[q], wx, wy);
                float2* wp = reinterpret_cast<float2*>(Wm + (kr0+q)*64 + 2*lane);
                float2 wv = *wp;
                wv.x -= wx; wv.y -= wy;
                *wp = wv;
                *reinterpret_cast<__half2*>((char*)sms + WH_OFF + (kr0+q)*144 + 4*lane) =
                    __halves2half2(__float2half_rn(wv.x), __float2half_rn(wv.y));
            }
            if (u == 0) *reinterpret_cast<float2*>(bbw + 2*lane) = make_float2(bx, by);
        }
        // next-iteration top __syncthreads covers all phase-C writes
    }
}

// ---------------- final layernorm over D, writes fp16 ----------------
__global__ __launch_bounds__(256)
void postln_half_kernel(const float* __restrict__ yin, const float* __restrict__ gmm,
                        const float* __restrict__ bta)
{
    __shared__ float red[8];
    int row = blockIdx.x, tid = threadIdx.x;
    const float* r = yin + (size_t)row * Dd;
    float vals[8];
    float s = 0.f;
    #pragma unroll
    for (int i = 0; i < 8; i++){ vals[i] = r[tid + 256*i]; s += vals[i]; }
    #pragma unroll
    for (int o = 16; o; o >>= 1) s += __shfl_xor_sync(0xffffffffu, s, o);
    if ((tid & 31) == 0) red[tid >> 5] = s;
    __syncthreads();
    float tot = 0.f;
    #pragma unroll
    for (int i = 0; i < 8; i++) tot += red[i];
    float mu = tot * (1.0f / (float)Dd);
    __syncthreads();
    float vs = 0.f;
    #pragma unroll
    for (int i = 0; i < 8; i++){ float d = vals[i] - mu; vs = fmaf(d, d, vs); }
    #pragma unroll
    for (int o = 16; o; o >>= 1) vs += __shfl_xor_sync(0xffffffffu, vs, o);
    if ((tid & 31) == 0) red[tid >> 5] = vs;
    __syncthreads();
    float vtot = 0.f;
    #pragma unroll
    for (int i = 0; i < 8; i++) vtot += red[i];
    float rstd = rsqrtf(vtot * (1.0f / (float)Dd) + EPSf);
    #pragma unroll
    for (int i = 0; i < 8; i++){
        int c = tid + 256*i;
        float val = fmaf(gmm[c] * (vals[i] - mu), rstd, bta[c]);
        g_xh[(size_t)row * Dd + c] = __float2half_rn(val);
    }
}

// ---------------- launch ----------------
extern "C" void kernel_launch(void* const* d_in, const int* in_sizes, int n_in,
                              void* d_out, int out_size)
{
    const float* x    = (const float*)d_in[0];
    const float* pf   = (const float*)d_in[1];
    const float* Wq   = (const float*)d_in[2];
    const float* Wk   = (const float*)d_in[3];
    const float* Wv   = (const float*)d_in[4];
    const float* Wo   = (const float*)d_in[5];
    const float* pg   = (const float*)d_in[6];
    const float* pb   = (const float*)d_in[7];
    const float* ilrW = (const float*)d_in[8];
    const float* ilrb = (const float*)d_in[9];
    const float* lgs  = (const float*)d_in[10];
    const float* tg   = (const float*)d_in[11];
    const float* tb   = (const float*)d_in[12];
    const float* W0   = (const float*)d_in[13];
    const float* b0   = (const float*)d_in[14];
    float* outp = (float*)d_out;

    float *qp, *yp;
    __half *xh, *wh, *qhp, *khp, *vhp;
    cudaGetSymbolAddress((void**)&qp, g_q);
    cudaGetSymbolAddress((void**)&yp, g_y);
    cudaGetSymbolAddress((void**)&xh, g_xh);
    cudaGetSymbolAddress((void**)&wh, g_wh);
    cudaGetSymbolAddress((void**)&qhp, g_qh);
    cudaGetSymbolAddress((void**)&khp, g_kh);
    cudaGetSymbolAddress((void**)&vhp, g_vh);

    cudaFuncSetAttribute(gemm_fp16<true>,  cudaFuncAttributeMaxDynamicSharedMemorySize, GSMEM);
    cudaFuncSetAttribute(gemm_fp16<false>, cudaFuncAttributeMaxDynamicSharedMemorySize, GSMEM);
    cudaFuncSetAttribute(scan_kernel, cudaFuncAttributeMaxDynamicSharedMemorySize, SCAN_SMEM_BYTES);
    cudaFuncSetAttribute(lr_kernel,   cudaFuncAttributeMaxDynamicSharedMemorySize, LRTOK*Dd*4);

    const int M = Bb * Ss;
    const int nw4 = (Dd * Dd) / 4;
    const int nx4 = (M * Dd) / 4;

    half_kernel<<<(nx4 + 255)/256, 256>>>(x, xh, nx4);
    dim3 wgrid((nw4 + 255)/256, 1, 4);
    halfw_kernel<<<wgrid, 256>>>(Wq, Wk, Wv, Wo, wh, nw4);
    ropetab_kernel<<<(Ss*32)/256, 256>>>(pf);

    dim3 ggrid(Dd / BNt, M / BMt, 3);    // (16, 32, 3)
    gemm_fp16<true><<<ggrid, 256, GSMEM>>>(xh, wh, qp, qhp, khp, vhp);

    lr_kernel<<<M / LRTOK, 256, LRTOK*Dd*4>>>(x, ilrW, ilrb);

    scan_kernel<<<Bb * Hh, 512, SCAN_SMEM_BYTES>>>(lgs, tg, tb, W0, b0);

    postln_half_kernel<<<M, 256>>>(yp, pg, pb);

    dim3 ogrid(Dd / BNt, M / BMt, 1);    // (16, 32, 1)
    gemm_fp16<false><<<ogrid, 256, GSMEM>>>(xh, wh + 3*(size_t)Dd*Dd, outp,
                                            nullptr, nullptr, nullptr);
}